// round 15
// baseline (speedup 1.0000x reference)
#include <cuda_runtime.h>
#include <cstdint>

// Problem constants
#define B_  256
#define C_  64
#define T_  406
#define D_  10
#define TD  4060          // T*D
#define KP  4608          // virtual K: [0,4060)=sp*m*x | [4060,4466)=mask | rest 0
#define ZSPLIT 18
#define ZCH 256           // KP / ZSPLIT
#define STG 128           // k-cols per smem stage (2 stages per chunk)
#define MBLK 16
#define NMB  16           // B_ / MBLK
#define LDS_ 132          // smem row stride (pad -> conflict-free frags)
#define NTHR 1024
#define NSLOT (4 * ZSPLIT) // partial slots: 4z+wg

// Output offsets (floats): output_seq, input_seq, loss, indices, label, mask, proto_count
#define O_OUT  0
#define O_IN   1039360
#define O_LOSS 2078720
#define O_IDX  2095104
#define O_LAB  2095360
#define O_MASK 2095616
#define O_PC   2199552

// gemm smem pool (words): Ys 16*132=2112 | Ps 64*132=8448 | s_sp 256
#define POOL_WORDS (2112 + 8448 + 256)
#define GEMM_SMEM (POOL_WORDS * 4)

// Static scratch (all quantities UNNORMALIZED; inv applied in loss epilogue)
__device__ __align__(16) float g_P[C_ * KP];    // P' rows: [p | -0.5*Qu | 0]
__device__ float g_spsum[4];                     // softplus partial sums
__device__ float g_part[NSLOT * B_ * C_];        // partials (slot 4z+wg)
__device__ float g_S1part[ZSPLIT * B_];          // S1u partials per z
__device__ unsigned g_cnt[NMB];                   // per M-block arrival counters

__device__ __forceinline__ uint32_t f2tf(float f) {
    uint32_t u;
    asm("cvt.rna.tf32.f32 %0, %1;" : "=r"(u) : "f"(f));
    return u;
}
__device__ __forceinline__ float softplus_f(float x) {
    return fmaxf(x, 0.f) + log1pf(expf(-fabsf(x)));   // jax softplus
}

// ---------------------------------------------------------------------------
// Kernel 1: prep (R11-R13 verbatim — passed).
// ---------------------------------------------------------------------------
__global__ void __launch_bounds__(256) prep_kernel(
    const float* __restrict__ x, const int* __restrict__ label,
    const float* __restrict__ mask, const float* __restrict__ proto,
    const float* __restrict__ w, const float* __restrict__ pcin,
    float* __restrict__ out)
{
    __shared__ float s_sp[1020];
    __shared__ float s_p[4][1020];
    __shared__ float s_red[8];
    __shared__ int s_cnt[C_];
    int bid = blockIdx.x, tid = threadIdx.x;

    if (bid < C_) {
        int cg = bid >> 2, tg = bid & 3;
        int c0 = cg * 4;
        int t0 = tg * 102;
        int t1 = (t0 + 102 < T_) ? t0 + 102 : T_;
        int nt = t1 - t0;
        int w0 = t0 * D_, nw = nt * D_;

        for (int j = tid; j < nw; j += 256) s_sp[j] = softplus_f(w[w0 + j]);

        {
            const float4* proto4 = (const float4*)proto;
            float4* gP4 = (float4*)g_P;
            int nq = nw >> 2, q0 = w0 >> 2;
            for (int idx = tid; idx < 4 * nq; idx += 256) {
                int rowl = idx / nq, q = idx - rowl * nq;
                float4 v = proto4[(size_t)(c0 + rowl) * (TD / 4) + q0 + q];
                *(float4*)&s_p[rowl][q * 4] = v;
                gP4[(size_t)(c0 + rowl) * (KP / 4) + q0 + q] = v;
            }
        }
        __syncthreads();

        #pragma unroll
        for (int cl = 0; cl < 4; cl++) {
            for (int tt = tid; tt < nt; tt += 256) {
                float q = 0.f;
                #pragma unroll
                for (int d = 0; d < D_; d++) {
                    float pv = s_p[cl][tt * D_ + d];
                    q = fmaf(s_sp[tt * D_ + d] * pv, pv, q);
                }
                g_P[(size_t)(c0 + cl) * KP + TD + t0 + tt] = -0.5f * q;
            }
        }
        if (tg == 3) {
            for (int k = TD + T_ + tid; k < KP; k += 256) {
                #pragma unroll
                for (int cl = 0; cl < 4; cl++)
                    g_P[(size_t)(c0 + cl) * KP + k] = 0.f;
            }
        }
        if (cg == 0) {
            float s = 0.f;
            for (int j = tid; j < nw; j += 256) s += s_sp[j];
            for (int o = 16; o; o >>= 1) s += __shfl_xor_sync(0xffffffffu, s, o);
            if ((tid & 31) == 0) s_red[tid >> 5] = s;
            __syncthreads();
            if (tid == 0) {
                float v = 0.f;
                #pragma unroll
                for (int i = 0; i < 8; i++) v += s_red[i];
                g_spsum[tg] = v;
            }
        }
    } else if (bid < C_ + B_) {
        int b = bid - C_;
        const float4* xs = (const float4*)(x + (size_t)b * TD);
        float4* oin = (float4*)(out + O_IN + (size_t)b * TD);
        for (int i = tid; i < TD / 4; i += 256) oin[i] = xs[i];
        for (int t = tid; t < T_; t += 256)
            out[O_MASK + (size_t)b * T_ + t] = mask[(size_t)b * T_ + t];

        int lab = label[b];
        const float4* ps = (const float4*)(proto + (size_t)lab * TD);
        float4* od = (float4*)(out + O_OUT + (size_t)b * TD);
        for (int i = tid; i < TD / 4; i += 256) od[i] = ps[i];
        if (tid == 0) {
            out[O_IDX + b] = (float)lab;               // K=1 -> indices == label
            out[O_LAB + b] = (float)lab;
        }
    } else {
        if (tid < C_) s_cnt[tid] = 0;
        __syncthreads();
        atomicAdd(&s_cnt[label[tid]], 1);              // 256 threads == B_
        __syncthreads();
        if (tid < C_) out[O_PC + tid] = pcin[tid] + (float)s_cnt[tid];
    }
}

// ---------------------------------------------------------------------------
// Kernel 2: tf32 split-K GEMM, 1024 threads / 32 warps, MBLK=16.
// grid = (16 m-blocks, 18 z) = 288 blocks -> 2 blocks/SM, 64 warps/SM.
// Stage = 128 cols (2 stages/chunk). 4 warp-groups (wg=wd>>3) each take a
// 32-col quarter of the stage; within a group 8 warps cover n=64 (tile 16x8).
// Y staged by threads tid<512 (row = tid>>5), P by all (2 float4/thread).
// Partials go to slot 4z+wg; fixed-order epilogue sum -> deterministic.
// FIX vs R14: __syncthreads() after s_sp fill BEFORE first store_stage
// (race: warps 8+ read s_sp written by warps 0-7).
// ---------------------------------------------------------------------------
__global__ void __launch_bounds__(NTHR) gemm_kernel(
    const float* __restrict__ x, const float* __restrict__ mask,
    const float* __restrict__ w, float* __restrict__ out)
{
    extern __shared__ float s_pool[];
    uint32_t (*Ys)[LDS_] = (uint32_t(*)[LDS_])s_pool;
    uint32_t (*Ps)[LDS_] = (uint32_t(*)[LDS_])(s_pool + MBLK * LDS_);
    float* s_sp = s_pool + MBLK * LDS_ + C_ * LDS_;
    __shared__ int s_last;

    int tid = threadIdx.x, lane = tid & 31, wd = tid >> 5;
    int bm0 = blockIdx.x * MBLK;
    int z = blockIdx.y, kz = z * ZCH;
    int wg = wd >> 3, wi = wd & 7;                 // 4 k-groups x 8 n-warps
    int wn = wi * 8;
    int g = lane >> 2, t4 = lane & 3;
    int srow = wd, sq = lane;                      // Y staging (warps 0-15 only)
    bool ystage = (tid < MBLK * 32);

    // local softplus chunk (256 values)
    if (tid < ZCH) {
        int k = kz + tid;
        s_sp[tid] = (k < TD) ? softplus_f(w[k]) : 0.f;
    }

    float acc[4] = {0.f, 0.f, 0.f, 0.f};
    float s1a = 0.f;

    // prefetch registers for one stage
    float4 xv, pv[2];
    float mv[4];
    int cur_k0 = 0;

    auto load_stage = [&](int st) {
        int k0 = kz + st * STG + sq * 4;
        cur_k0 = k0;
        if (ystage) {
            int r = bm0 + srow;
            if (k0 < TD) {
                xv = *(const float4*)&x[(size_t)r * TD + k0];
                #pragma unroll
                for (int j = 0; j < 4; j++)
                    mv[j] = __ldg(&mask[(size_t)r * T_ + (k0 + j) / D_]);
            } else {
                #pragma unroll
                for (int j = 0; j < 4; j++) {
                    int k = k0 + j;
                    mv[j] = (k < TD + T_) ? __ldg(&mask[(size_t)r * T_ + (k - TD)])
                                          : 0.f;
                }
            }
        }
        // P: 64 rows x 32 quads = 2048 float4, 2 per thread
        #pragma unroll
        for (int i = 0; i < 2; i++) {
            int u = tid + i * NTHR;
            int pr = u >> 5, pq = u & 31;
            pv[i] = *(const float4*)&g_P[(size_t)pr * KP + kz + st * STG + pq * 4];
        }
    };

    auto store_stage = [&]() {
        if (ystage) {
            float y[4];
            if (cur_k0 < TD) {
                float xx[4] = { xv.x, xv.y, xv.z, xv.w };
                #pragma unroll
                for (int j = 0; j < 4; j++) {
                    float yv = mv[j] * s_sp[cur_k0 - kz + j] * xx[j];
                    y[j] = yv;
                    s1a = fmaf(yv, xx[j], s1a);
                }
            } else {
                #pragma unroll
                for (int j = 0; j < 4; j++) y[j] = mv[j];
            }
            uint4 u = { f2tf(y[0]), f2tf(y[1]), f2tf(y[2]), f2tf(y[3]) };
            *(uint4*)&Ys[srow][sq * 4] = u;
        }
        #pragma unroll
        for (int i = 0; i < 2; i++) {
            int uu = tid + i * NTHR;
            int pr = uu >> 5, pq = uu & 31;
            uint4 up = { f2tf(pv[i].x), f2tf(pv[i].y), f2tf(pv[i].z), f2tf(pv[i].w) };
            *(uint4*)&Ps[pr][pq * 4] = up;
        }
    };

    __syncthreads();     // s_sp visible to ALL warps before store_stage reads it
    load_stage(0);
    #pragma unroll
    for (int st = 0; st < ZCH / STG; st++) {
        store_stage();
        __syncthreads();
        if (st < ZCH / STG - 1) load_stage(st + 1);   // overlaps with mma below
        int kbase = wg * 32;
        #pragma unroll
        for (int kk = 0; kk < 32; kk += 8) {
            int kc = kbase + kk;
            uint32_t a0 = Ys[g][kc + t4];
            uint32_t a1 = Ys[g + 8][kc + t4];
            uint32_t a2 = Ys[g][kc + t4 + 4];
            uint32_t a3 = Ys[g + 8][kc + t4 + 4];
            uint32_t b0 = Ps[wn + g][kc + t4];
            uint32_t b1 = Ps[wn + g][kc + t4 + 4];
            asm("mma.sync.aligned.m16n8k8.row.col.f32.tf32.tf32.f32 "
                "{%0,%1,%2,%3}, {%4,%5,%6,%7}, {%8,%9}, {%0,%1,%2,%3};"
                : "+f"(acc[0]), "+f"(acc[1]), "+f"(acc[2]), "+f"(acc[3])
                : "r"(a0), "r"(a1), "r"(a2), "r"(a3), "r"(b0), "r"(b1));
        }
        __syncthreads();
    }

    // GEMM partials (slot 4z+wg)
    float* part = g_part + (size_t)(4 * z + wg) * B_ * C_;
    int orow = bm0 + g;
    int col = wn + 2 * t4;
    *(float2*)&part[orow * C_ + col]       = make_float2(acc[0], acc[1]);
    *(float2*)&part[(orow + 8) * C_ + col] = make_float2(acc[2], acc[3]);

    // S1u partials: warp wd (<16) staged row wd -> full-warp reduce
    if (ystage) {
        float v = s1a;
        #pragma unroll
        for (int o = 16; o; o >>= 1) v += __shfl_xor_sync(0xffffffffu, v, o);
        if (lane == 0) g_S1part[z * B_ + bm0 + srow] = v;
    }

    // last-z-block-done loss epilogue (atomicInc wraps -> replay-safe)
    __threadfence();
    __syncthreads();
    if (tid == 0) {
        unsigned old = atomicInc(&g_cnt[blockIdx.x], ZSPLIT - 1);
        s_last = (old == ZSPLIT - 1);
    }
    __syncthreads();
    if (s_last) {
        float inv = 1.f / (__ldg(&g_spsum[0]) + __ldg(&g_spsum[1]) +
                           __ldg(&g_spsum[2]) + __ldg(&g_spsum[3]));
        for (int o = tid; o < MBLK * C_; o += NTHR) {
            int b = bm0 + (o >> 6), c = o & 63;
            float s = 0.f, s1 = 0.f;
            #pragma unroll
            for (int zz = 0; zz < NSLOT; zz++)
                s += __ldcg(&g_part[(size_t)zz * B_ * C_ + b * C_ + c]);
            #pragma unroll
            for (int zz = 0; zz < ZSPLIT; zz++)
                s1 += __ldcg(&g_S1part[zz * B_ + b]);
            out[O_LOSS + b * C_ + c] = inv * (s1 - 2.f * s);
        }
    }
}

// ---------------------------------------------------------------------------
extern "C" void kernel_launch(void* const* d_in, const int* in_sizes, int n_in,
                              void* d_out, int out_size) {
    const float* input_seq  = (const float*)d_in[0];
    const int*   label      = (const int*)  d_in[1];
    const float* mask       = (const float*)d_in[2];
    const float* prototypes = (const float*)d_in[3];
    const float* weights    = (const float*)d_in[4];
    const float* protocount = (const float*)d_in[5];
    float* out = (float*)d_out;

    prep_kernel<<<C_ + B_ + 1, 256>>>(input_seq, label, mask, prototypes,
                                      weights, protocount, out);
    cudaFuncSetAttribute(gemm_kernel,
                         cudaFuncAttributeMaxDynamicSharedMemorySize, GEMM_SMEM);
    gemm_kernel<<<dim3(NMB, ZSPLIT), NTHR, GEMM_SMEM>>>(input_seq, mask,
                                                        weights, out);
}

// round 16
// speedup vs baseline: 1.2072x; 1.2072x over previous
#include <cuda_runtime.h>
#include <cstdint>

// Problem constants
#define B_  256
#define C_  64
#define T_  406
#define D_  10
#define TD  4060          // T*D
#define KP  4608          // virtual K: [0,4060)=sp*m*x | [4060,4466)=mask | rest 0
#define ZSPLIT 18
#define ZCH 256           // KP / ZSPLIT
#define STG 128           // k-cols per smem stage (2 stages per chunk)
#define MBLK 32
#define LDS_ 132          // smem row stride (pad -> conflict-free frags)
#define NTHR 1024

#define N_GEMM 144                    // 8 m-blocks x 18 z
#define N_COPY 64                     // 64 blocks x 4 samples
#define N_BLOCKS (N_GEMM + N_COPY + 1)

// Output offsets (floats): output_seq, input_seq, loss, indices, label, mask, proto_count
#define O_OUT  0
#define O_IN   1039360
#define O_LOSS 2078720
#define O_IDX  2095104
#define O_LAB  2095360
#define O_MASK 2095616
#define O_PC   2199552

// gemm smem pool (words): Ys 32*132=4224 | Ps 64*132=8448 | s_sp 256
#define POOL_WORDS (4224 + 8448 + 256)
#define GEMM_SMEM (POOL_WORDS * 4)

// Static scratch (all quantities UNNORMALIZED; inv applied in loss epilogue)
__device__ __align__(16) uint32_t g_P[C_ * KP];  // P' rows, tf32 PRE-CONVERTED
__device__ float g_spsum[4];                      // softplus partial sums
__device__ float g_part[2 * ZSPLIT * B_ * C_];    // partials (slot 2z+wg)
__device__ float g_S1part[ZSPLIT * B_];           // S1u partials per z
__device__ unsigned g_cnt[8];                      // per M-block arrival counters

__device__ __forceinline__ uint32_t f2tf(float f) {
    uint32_t u;
    asm("cvt.rna.tf32.f32 %0, %1;" : "=r"(u) : "f"(f));
    return u;
}
__device__ __forceinline__ float softplus_f(float x) {
    return fmaxf(x, 0.f) + log1pf(expf(-fabsf(x)));   // jax softplus
}

// ---------------------------------------------------------------------------
// Kernel 1: prep — P'-build ONLY (64 blocks; copies moved to kernel 2).
// Block (cg=bid>>2 -> 4 c-rows, tg=bid&3 -> ~102 t): local softplus,
// p-cols tf32-converted into g_P, -0.5*Qu mask-cols, tg3 zero-pads,
// cg0 writes spsum partial.
// ---------------------------------------------------------------------------
__global__ void __launch_bounds__(256) prep_kernel(
    const float* __restrict__ proto, const float* __restrict__ w)
{
    __shared__ float s_sp[1020];
    __shared__ float s_p[4][1020];
    __shared__ float s_red[8];
    int bid = blockIdx.x, tid = threadIdx.x;

    int cg = bid >> 2, tg = bid & 3;
    int c0 = cg * 4;
    int t0 = tg * 102;
    int t1 = (t0 + 102 < T_) ? t0 + 102 : T_;
    int nt = t1 - t0;
    int w0 = t0 * D_, nw = nt * D_;

    for (int j = tid; j < nw; j += 256) s_sp[j] = softplus_f(w[w0 + j]);

    {
        const float4* proto4 = (const float4*)proto;
        uint4* gP4 = (uint4*)g_P;
        int nq = nw >> 2, q0 = w0 >> 2;
        for (int idx = tid; idx < 4 * nq; idx += 256) {
            int rowl = idx / nq, q = idx - rowl * nq;
            float4 v = proto4[(size_t)(c0 + rowl) * (TD / 4) + q0 + q];
            *(float4*)&s_p[rowl][q * 4] = v;
            uint4 uv = { f2tf(v.x), f2tf(v.y), f2tf(v.z), f2tf(v.w) };
            gP4[(size_t)(c0 + rowl) * (KP / 4) + q0 + q] = uv;
        }
    }
    __syncthreads();

    #pragma unroll
    for (int cl = 0; cl < 4; cl++) {
        for (int tt = tid; tt < nt; tt += 256) {
            float q = 0.f;
            #pragma unroll
            for (int d = 0; d < D_; d++) {
                float pv = s_p[cl][tt * D_ + d];
                q = fmaf(s_sp[tt * D_ + d] * pv, pv, q);
            }
            g_P[(size_t)(c0 + cl) * KP + TD + t0 + tt] = f2tf(-0.5f * q);
        }
    }
    if (tg == 3) {
        for (int k = TD + T_ + tid; k < KP; k += 256) {
            #pragma unroll
            for (int cl = 0; cl < 4; cl++)
                g_P[(size_t)(c0 + cl) * KP + k] = 0u;
        }
    }
    if (cg == 0) {
        float s = 0.f;
        for (int j = tid; j < nw; j += 256) s += s_sp[j];
        for (int o = 16; o; o >>= 1) s += __shfl_xor_sync(0xffffffffu, s, o);
        if ((tid & 31) == 0) s_red[tid >> 5] = s;
        __syncthreads();
        if (tid == 0) {
            float v = 0.f;
            #pragma unroll
            for (int i = 0; i < 8; i++) v += s_red[i];
            g_spsum[tg] = v;
        }
    }
}

// ---------------------------------------------------------------------------
// Kernel 2: tf32 split-K GEMM (R13 core + R15 sync fix) + backfill copies.
//  bid < 144:        gemm block m=bid&7, z=bid>>3. 1024 thr / 32 warps.
//                    Stage=128 cols (2/chunk); wg=wd>>4 takes a 64-col half,
//                    wi=wd&15 -> 2m x 8n warp grid (tile 16x8). P staged from
//                    pre-converted g_P (no cvt). Partials slot 2z+wg.
//  144 <= bid < 208: copy block (4 samples each; sub-group of 256 thr/sample)
//  bid == 208:       proto_count
// ---------------------------------------------------------------------------
__global__ void __launch_bounds__(NTHR) gemm_kernel(
    const float* __restrict__ x, const int* __restrict__ label,
    const float* __restrict__ mask, const float* __restrict__ proto,
    const float* __restrict__ w, const float* __restrict__ pcin,
    float* __restrict__ out)
{
    extern __shared__ float s_pool[];
    __shared__ int s_last;
    __shared__ int s_cnt[C_];

    int bid = blockIdx.x, tid = threadIdx.x;

    if (bid >= N_GEMM) {
        if (bid < N_GEMM + N_COPY) {
            // ---------------- copy block: 4 samples ----------------
            int b = (bid - N_GEMM) * 4 + (tid >> 8);
            int stid = tid & 255;
            const float4* xs = (const float4*)(x + (size_t)b * TD);
            float4* oin = (float4*)(out + O_IN + (size_t)b * TD);
            for (int i = stid; i < TD / 4; i += 256) oin[i] = xs[i];
            for (int t = stid; t < T_; t += 256)
                out[O_MASK + (size_t)b * T_ + t] = mask[(size_t)b * T_ + t];
            int lab = label[b];
            const float4* ps = (const float4*)(proto + (size_t)lab * TD);
            float4* od = (float4*)(out + O_OUT + (size_t)b * TD);
            for (int i = stid; i < TD / 4; i += 256) od[i] = ps[i];
            if (stid == 0) {
                out[O_IDX + b] = (float)lab;   // K=1 -> indices == label
                out[O_LAB + b] = (float)lab;
            }
        } else {
            // ---------------- proto_count ----------------
            if (tid < C_) s_cnt[tid] = 0;
            __syncthreads();
            if (tid < B_) atomicAdd(&s_cnt[label[tid]], 1);
            __syncthreads();
            if (tid < C_) out[O_PC + tid] = pcin[tid] + (float)s_cnt[tid];
        }
        return;
    }

    // ---------------- GEMM block ----------------
    uint32_t (*Ys)[LDS_] = (uint32_t(*)[LDS_])s_pool;
    uint32_t (*Ps)[LDS_] = (uint32_t(*)[LDS_])(s_pool + MBLK * LDS_);
    float* s_sp = s_pool + MBLK * LDS_ + C_ * LDS_;

    int lane = tid & 31, wd = tid >> 5;
    int m = bid & 7, z = bid >> 3;
    int bm0 = m * MBLK;
    int kz = z * ZCH;
    int wg = wd >> 4, wi = wd & 15;
    int wm = (wi & 1) * 16, wn = (wi >> 1) * 8;    // 2m x 8n per half
    int g = lane >> 2, t4 = lane & 3;
    int srow = wd, sq = lane;                      // staging: warp wd = row wd

    // local softplus chunk (256 values)
    if (tid < ZCH) {
        int k = kz + tid;
        s_sp[tid] = (k < TD) ? softplus_f(w[k]) : 0.f;
    }

    float acc[4] = {0.f, 0.f, 0.f, 0.f};
    float s1a = 0.f;

    // prefetch registers for one stage (1 Y float4 + 2 P uint4 per thread)
    float4 xv;
    uint4 pu[2];
    float mv[4];
    int cur_k0 = 0;

    auto load_stage = [&](int st) {
        int k0 = kz + st * STG + sq * 4;
        cur_k0 = k0;
        int r = bm0 + srow;
        if (k0 < TD) {
            xv = *(const float4*)&x[(size_t)r * TD + k0];
            #pragma unroll
            for (int j = 0; j < 4; j++)
                mv[j] = __ldg(&mask[(size_t)r * T_ + (k0 + j) / D_]);
        } else {
            #pragma unroll
            for (int j = 0; j < 4; j++) {
                int k = k0 + j;
                mv[j] = (k < TD + T_) ? __ldg(&mask[(size_t)r * T_ + (k - TD)])
                                      : 0.f;
            }
        }
        // P: 64 rows x 32 quads = 2048 uint4, 2 per thread (pre-converted)
        #pragma unroll
        for (int i = 0; i < 2; i++) {
            int u = tid + i * NTHR;
            int pr = u >> 5, pq = u & 31;
            pu[i] = *(const uint4*)&g_P[(size_t)pr * KP + kz + st * STG + pq * 4];
        }
    };

    auto store_stage = [&]() {
        float y[4];
        if (cur_k0 < TD) {
            float xx[4] = { xv.x, xv.y, xv.z, xv.w };
            #pragma unroll
            for (int j = 0; j < 4; j++) {
                float yv = mv[j] * s_sp[cur_k0 - kz + j] * xx[j];
                y[j] = yv;
                s1a = fmaf(yv, xx[j], s1a);
            }
        } else {
            #pragma unroll
            for (int j = 0; j < 4; j++) y[j] = mv[j];
        }
        uint4 u = { f2tf(y[0]), f2tf(y[1]), f2tf(y[2]), f2tf(y[3]) };
        *(uint4*)&Ys[srow][sq * 4] = u;
        #pragma unroll
        for (int i = 0; i < 2; i++) {
            int uu = tid + i * NTHR;
            int pr = uu >> 5, pq = uu & 31;
            *(uint4*)&Ps[pr][pq * 4] = pu[i];
        }
    };

    load_stage(0);
    __syncthreads();     // s_sp visible to ALL warps before store_stage reads it
    #pragma unroll
    for (int st = 0; st < ZCH / STG; st++) {
        store_stage();
        __syncthreads();
        if (st < ZCH / STG - 1) load_stage(st + 1);   // overlaps with mma below
        int kbase = wg * 64;
        #pragma unroll
        for (int kk = 0; kk < 64; kk += 8) {
            int kc = kbase + kk;
            uint32_t a0 = Ys[wm + g][kc + t4];
            uint32_t a1 = Ys[wm + g + 8][kc + t4];
            uint32_t a2 = Ys[wm + g][kc + t4 + 4];
            uint32_t a3 = Ys[wm + g + 8][kc + t4 + 4];
            uint32_t b0 = Ps[wn + g][kc + t4];
            uint32_t b1 = Ps[wn + g][kc + t4 + 4];
            asm("mma.sync.aligned.m16n8k8.row.col.f32.tf32.tf32.f32 "
                "{%0,%1,%2,%3}, {%4,%5,%6,%7}, {%8,%9}, {%0,%1,%2,%3};"
                : "+f"(acc[0]), "+f"(acc[1]), "+f"(acc[2]), "+f"(acc[3])
                : "r"(a0), "r"(a1), "r"(a2), "r"(a3), "r"(b0), "r"(b1));
        }
        __syncthreads();
    }

    // GEMM partials (slot 2z+wg)
    float* part = g_part + (size_t)(2 * z + wg) * B_ * C_;
    int orow = bm0 + wm + g;
    int col = wn + 2 * t4;
    *(float2*)&part[orow * C_ + col]       = make_float2(acc[0], acc[1]);
    *(float2*)&part[(orow + 8) * C_ + col] = make_float2(acc[2], acc[3]);

    // S1u partials: warp wd staged row wd -> full-warp reduce, lane0 writes
    {
        float v = s1a;
        #pragma unroll
        for (int o = 16; o; o >>= 1) v += __shfl_xor_sync(0xffffffffu, v, o);
        if (lane == 0) g_S1part[z * B_ + bm0 + srow] = v;
    }

    // last-z-block-done loss epilogue (atomicInc wraps -> replay-safe)
    __threadfence();
    __syncthreads();
    if (tid == 0) {
        unsigned old = atomicInc(&g_cnt[m], ZSPLIT - 1);
        s_last = (old == ZSPLIT - 1);
    }
    __syncthreads();
    if (s_last) {
        float inv = 1.f / (__ldg(&g_spsum[0]) + __ldg(&g_spsum[1]) +
                           __ldg(&g_spsum[2]) + __ldg(&g_spsum[3]));
        for (int o = tid; o < MBLK * C_; o += NTHR) {
            int b = bm0 + (o >> 6), c = o & 63;
            float s = 0.f, s1 = 0.f;
            #pragma unroll
            for (int zz = 0; zz < 2 * ZSPLIT; zz++)
                s += __ldcg(&g_part[(size_t)zz * B_ * C_ + b * C_ + c]);
            #pragma unroll
            for (int zz = 0; zz < ZSPLIT; zz++)
                s1 += __ldcg(&g_S1part[zz * B_ + b]);
            out[O_LOSS + b * C_ + c] = inv * (s1 - 2.f * s);
        }
    }
}

// ---------------------------------------------------------------------------
extern "C" void kernel_launch(void* const* d_in, const int* in_sizes, int n_in,
                              void* d_out, int out_size) {
    const float* input_seq  = (const float*)d_in[0];
    const int*   label      = (const int*)  d_in[1];
    const float* mask       = (const float*)d_in[2];
    const float* prototypes = (const float*)d_in[3];
    const float* weights    = (const float*)d_in[4];
    const float* protocount = (const float*)d_in[5];
    float* out = (float*)d_out;

    prep_kernel<<<C_, 256>>>(prototypes, weights);
    cudaFuncSetAttribute(gemm_kernel,
                         cudaFuncAttributeMaxDynamicSharedMemorySize, GEMM_SMEM);
    gemm_kernel<<<N_BLOCKS, NTHR, GEMM_SMEM>>>(input_seq, label, mask,
                                               prototypes, weights,
                                               protocount, out);
}

// round 17
// speedup vs baseline: 1.2240x; 1.0139x over previous
#include <cuda_runtime.h>
#include <cstdint>

// Problem constants
#define B_  256
#define C_  64
#define T_  406
#define D_  10
#define TD  4060          // T*D
#define KPAD 4096         // padded K (tail zero)
#define ZSPLIT 16
#define ZCH 256           // KPAD / ZSPLIT
#define STG 128           // k-cols per smem stage (2 stages per chunk)
#define MBLK 32
#define LDS_ 132          // smem row stride (pad -> conflict-free frags)
#define NTHR 1024

#define N_GEMM 128                    // 8 m-blocks x 16 z
#define N_COPY 64                     // 64 blocks x 4 samples
#define N_BLOCKS (N_GEMM + N_COPY + 1)

// Output offsets (floats): output_seq, input_seq, loss, indices, label, mask, proto_count
#define O_OUT  0
#define O_IN   1039360
#define O_LOSS 2078720
#define O_IDX  2095104
#define O_LAB  2095360
#define O_MASK 2095616
#define O_PC   2199552

// smem pool (words): Ys 32*132 | Y2s 32*132 | Ps 64*132 | P2s 64*132 | s_sp 256
#define W_YS   (MBLK * LDS_)
#define W_PS   (C_ * LDS_)
#define POOL_WORDS (2 * W_YS + 2 * W_PS + 256)
#define GEMM_SMEM (POOL_WORDS * 4)

// Static scratch (all UNNORMALIZED; inv applied in loss epilogue)
__device__ float g_spsum[ZSPLIT];                 // sp-sum per z (redundant writes)
__device__ float g_part[2 * ZSPLIT * B_ * C_];    // partials (slot 2z+wg)
__device__ float g_S1part[ZSPLIT * B_];           // S1u partials per z
__device__ unsigned g_cnt[8];                      // per M-block arrival counters

__device__ __forceinline__ uint32_t f2tf(float f) {
    uint32_t u;
    asm("cvt.rna.tf32.f32 %0, %1;" : "=r"(u) : "f"(f));
    return u;
}
__device__ __forceinline__ float softplus_f(float x) {
    return fmaxf(x, 0.f) + log1pf(expf(-fabsf(x)));   // jax softplus
}

// ---------------------------------------------------------------------------
// SINGLE kernel.
//  bid < 128:        gemm block m=bid&7, z=bid>>3. 1024 thr / 32 warps.
//                    Dual-GEMM into one acc: (-2*m*sp*x)@p  +  (m*sp)@(p^2),
//                    both operands staged from RAW inputs (no precompute).
//  128 <= bid < 192: copy block (4 samples each)
//  bid == 192:       proto_count
// ---------------------------------------------------------------------------
__global__ void __launch_bounds__(NTHR) fused_kernel(
    const float* __restrict__ x, const int* __restrict__ label,
    const float* __restrict__ mask, const float* __restrict__ proto,
    const float* __restrict__ w, const float* __restrict__ pcin,
    float* __restrict__ out)
{
    extern __shared__ float s_pool[];
    __shared__ int s_last;
    __shared__ int s_cnt[C_];
    __shared__ float s_red[8];

    int bid = blockIdx.x, tid = threadIdx.x;

    if (bid >= N_GEMM) {
        if (bid < N_GEMM + N_COPY) {
            // ---------------- copy block: 4 samples ----------------
            int b = (bid - N_GEMM) * 4 + (tid >> 8);
            int stid = tid & 255;
            const float4* xs = (const float4*)(x + (size_t)b * TD);
            float4* oin = (float4*)(out + O_IN + (size_t)b * TD);
            for (int i = stid; i < TD / 4; i += 256) oin[i] = xs[i];
            for (int t = stid; t < T_; t += 256)
                out[O_MASK + (size_t)b * T_ + t] = mask[(size_t)b * T_ + t];
            int lab = label[b];
            const float4* ps = (const float4*)(proto + (size_t)lab * TD);
            float4* od = (float4*)(out + O_OUT + (size_t)b * TD);
            for (int i = stid; i < TD / 4; i += 256) od[i] = ps[i];
            if (stid == 0) {
                out[O_IDX + b] = (float)lab;   // K=1 -> indices == label
                out[O_LAB + b] = (float)lab;
            }
        } else {
            // ---------------- proto_count ----------------
            if (tid < C_) s_cnt[tid] = 0;
            __syncthreads();
            if (tid < B_) atomicAdd(&s_cnt[label[tid]], 1);
            __syncthreads();
            if (tid < C_) out[O_PC + tid] = pcin[tid] + (float)s_cnt[tid];
        }
        return;
    }

    // ---------------- GEMM block ----------------
    uint32_t (*Ys)[LDS_]  = (uint32_t(*)[LDS_])s_pool;
    uint32_t (*Y2s)[LDS_] = (uint32_t(*)[LDS_])(s_pool + W_YS);
    uint32_t (*Ps)[LDS_]  = (uint32_t(*)[LDS_])(s_pool + 2 * W_YS);
    uint32_t (*P2s)[LDS_] = (uint32_t(*)[LDS_])(s_pool + 2 * W_YS + W_PS);
    float* s_sp = s_pool + 2 * W_YS + 2 * W_PS;

    int lane = tid & 31, wd = tid >> 5;
    int m = bid & 7, z = bid >> 3;
    int bm0 = m * MBLK;
    int kz = z * ZCH;
    int wg = wd >> 4, wi = wd & 15;
    int wm = (wi & 1) * 16, wn = (wi >> 1) * 8;    // 2m x 8n per k-half
    int g = lane >> 2, t4 = lane & 3;
    int srow = wd, sq = lane;                      // staging: warp wd = Y row wd

    // local softplus chunk (256 values, unnormalized)
    if (tid < ZCH) {
        int k = kz + tid;
        s_sp[tid] = (k < TD) ? softplus_f(w[k]) : 0.f;
    }

    float acc[4] = {0.f, 0.f, 0.f, 0.f};
    float s1a = 0.f;

    // prefetch registers (1 Y float4 + 4 mask + 2 P float4 per thread)
    float4 xv, pv[2];
    float mv[4];
    int cur_k0 = 0;

    auto load_stage = [&](int st) {
        int k0 = kz + st * STG + sq * 4;
        cur_k0 = k0;
        int r = bm0 + srow;
        if (k0 < TD) {                               // TD%4==0: full float4 valid
            xv = *(const float4*)&x[(size_t)r * TD + k0];
            #pragma unroll
            for (int j = 0; j < 4; j++)
                mv[j] = __ldg(&mask[(size_t)r * T_ + (k0 + j) / D_]);
        }
        // P: 64 rows x 32 quads = 2048 float4, 2 per thread, from RAW proto
        #pragma unroll
        for (int i = 0; i < 2; i++) {
            int u = tid + i * NTHR;
            int pr = u >> 5, pq = u & 31;
            int kp = kz + st * STG + pq * 4;
            if (kp < TD)
                pv[i] = *(const float4*)&proto[(size_t)pr * TD + kp];
            else
                pv[i] = make_float4(0.f, 0.f, 0.f, 0.f);
        }
    };

    auto store_stage = [&]() {
        float y[4], y2[4];
        if (cur_k0 < TD) {
            float xx[4] = { xv.x, xv.y, xv.z, xv.w };
            #pragma unroll
            for (int j = 0; j < 4; j++) {
                float msp = mv[j] * s_sp[cur_k0 - kz + j];   // mask*sp
                s1a = fmaf(msp * xx[j], xx[j], s1a);         // S1u += m*sp*x^2
                y[j]  = -2.f * msp * xx[j];
                y2[j] = msp;
            }
        } else {
            #pragma unroll
            for (int j = 0; j < 4; j++) { y[j] = 0.f; y2[j] = 0.f; }
        }
        uint4 uy  = { f2tf(y[0]),  f2tf(y[1]),  f2tf(y[2]),  f2tf(y[3]) };
        uint4 uy2 = { f2tf(y2[0]), f2tf(y2[1]), f2tf(y2[2]), f2tf(y2[3]) };
        *(uint4*)&Ys[srow][sq * 4]  = uy;
        *(uint4*)&Y2s[srow][sq * 4] = uy2;
        #pragma unroll
        for (int i = 0; i < 2; i++) {
            int uu = tid + i * NTHR;
            int pr = uu >> 5, pq = uu & 31;
            uint4 up  = { f2tf(pv[i].x), f2tf(pv[i].y),
                          f2tf(pv[i].z), f2tf(pv[i].w) };
            uint4 up2 = { f2tf(pv[i].x * pv[i].x), f2tf(pv[i].y * pv[i].y),
                          f2tf(pv[i].z * pv[i].z), f2tf(pv[i].w * pv[i].w) };
            *(uint4*)&Ps[pr][pq * 4]  = up;
            *(uint4*)&P2s[pr][pq * 4] = up2;
        }
    };

    load_stage(0);
    __syncthreads();     // s_sp visible to ALL warps before store_stage reads it
    #pragma unroll
    for (int st = 0; st < ZCH / STG; st++) {
        store_stage();
        __syncthreads();
        if (st < ZCH / STG - 1) load_stage(st + 1);   // overlaps with mma below
        int kbase = wg * 64;
        #pragma unroll
        for (int kk = 0; kk < 64; kk += 8) {
            int kc = kbase + kk;
            uint32_t a0 = Ys[wm + g][kc + t4];
            uint32_t a1 = Ys[wm + g + 8][kc + t4];
            uint32_t a2 = Ys[wm + g][kc + t4 + 4];
            uint32_t a3 = Ys[wm + g + 8][kc + t4 + 4];
            uint32_t b0 = Ps[wn + g][kc + t4];
            uint32_t b1 = Ps[wn + g][kc + t4 + 4];
            asm("mma.sync.aligned.m16n8k8.row.col.f32.tf32.tf32.f32 "
                "{%0,%1,%2,%3}, {%4,%5,%6,%7}, {%8,%9}, {%0,%1,%2,%3};"
                : "+f"(acc[0]), "+f"(acc[1]), "+f"(acc[2]), "+f"(acc[3])
                : "r"(a0), "r"(a1), "r"(a2), "r"(a3), "r"(b0), "r"(b1));
            uint32_t c0 = Y2s[wm + g][kc + t4];
            uint32_t c1 = Y2s[wm + g + 8][kc + t4];
            uint32_t c2 = Y2s[wm + g][kc + t4 + 4];
            uint32_t c3 = Y2s[wm + g + 8][kc + t4 + 4];
            uint32_t d0 = P2s[wn + g][kc + t4];
            uint32_t d1 = P2s[wn + g][kc + t4 + 4];
            asm("mma.sync.aligned.m16n8k8.row.col.f32.tf32.tf32.f32 "
                "{%0,%1,%2,%3}, {%4,%5,%6,%7}, {%8,%9}, {%0,%1,%2,%3};"
                : "+f"(acc[0]), "+f"(acc[1]), "+f"(acc[2]), "+f"(acc[3])
                : "r"(c0), "r"(c1), "r"(c2), "r"(c3), "r"(d0), "r"(d1));
        }
        __syncthreads();
    }

    // GEMM partials (slot 2z+wg)
    float* part = g_part + (size_t)(2 * z + wg) * B_ * C_;
    int orow = bm0 + wm + g;
    int col = wn + 2 * t4;
    *(float2*)&part[orow * C_ + col]       = make_float2(acc[0], acc[1]);
    *(float2*)&part[(orow + 8) * C_ + col] = make_float2(acc[2], acc[3]);

    // S1u partials: warp wd staged row wd -> full-warp reduce, lane0 writes
    {
        float v = s1a;
        #pragma unroll
        for (int o = 16; o; o >>= 1) v += __shfl_xor_sync(0xffffffffu, v, o);
        if (lane == 0) g_S1part[z * B_ + bm0 + srow] = v;
    }

    // sp-chunk sum -> g_spsum[z]. Identical deterministic value from every m
    // (same data, same order) -> redundant writes are benign.
    if (tid < ZCH) {
        float s = s_sp[tid];
        for (int o = 16; o; o >>= 1) s += __shfl_xor_sync(0xffffffffu, s, o);
        if (lane == 0) s_red[wd] = s;
    }
    __syncthreads();
    if (tid == 0) {
        float v = 0.f;
        #pragma unroll
        for (int i = 0; i < 8; i++) v += s_red[i];
        g_spsum[z] = v;
    }

    // last-z-block-done loss epilogue (atomicInc wraps -> replay-safe)
    __threadfence();
    __syncthreads();
    if (tid == 0) {
        unsigned old = atomicInc(&g_cnt[m], ZSPLIT - 1);
        s_last = (old == ZSPLIT - 1);
    }
    __syncthreads();
    if (s_last) {
        float tot = 0.f;
        #pragma unroll
        for (int i = 0; i < ZSPLIT; i++) tot += __ldcg(&g_spsum[i]);
        float inv = 1.f / tot;
        for (int o = tid; o < MBLK * C_; o += NTHR) {
            int b = bm0 + (o >> 6), c = o & 63;
            float s = 0.f, s1 = 0.f;
            #pragma unroll
            for (int zz = 0; zz < 2 * ZSPLIT; zz++)
                s += __ldcg(&g_part[(size_t)zz * B_ * C_ + b * C_ + c]);
            #pragma unroll
            for (int zz = 0; zz < ZSPLIT; zz++)
                s1 += __ldcg(&g_S1part[zz * B_ + b]);
            out[O_LOSS + b * C_ + c] = inv * (s1 + s);   // s = -2*XP + MQ
        }
    }
}

// ---------------------------------------------------------------------------
extern "C" void kernel_launch(void* const* d_in, const int* in_sizes, int n_in,
                              void* d_out, int out_size) {
    const float* input_seq  = (const float*)d_in[0];
    const int*   label      = (const int*)  d_in[1];
    const float* mask       = (const float*)d_in[2];
    const float* prototypes = (const float*)d_in[3];
    const float* weights    = (const float*)d_in[4];
    const float* protocount = (const float*)d_in[5];
    float* out = (float*)d_out;

    cudaFuncSetAttribute(fused_kernel,
                         cudaFuncAttributeMaxDynamicSharedMemorySize, GEMM_SMEM);
    fused_kernel<<<N_BLOCKS, NTHR, GEMM_SMEM>>>(input_seq, label, mask,
                                                prototypes, weights,
                                                protocount, out);
}